// round 10
// baseline (speedup 1.0000x reference)
#include <cuda_runtime.h>

// FOG: stride-2 occupancy downsample of 4M sparse voxels.
// v6: self-contained 32B sectors [prefix u32 | 7x u32 bitmap words] = 224 keys.
// Rank query in pass B = ONE 32B sector load (was bitmap sector + prefix sector).

#define HALF 512u
#define KPS 224u                       // keys per sector
#define NSEC 2396746u                  // ceil(2^29 / 224)
#define SCT 512
#define SEC_PER_T 4
#define TILE_SECS (SCT * SEC_PER_T)    // 2048 sectors per scan tile
#define NTILES ((NSEC + TILE_SECS - 1u) / TILE_SECS)   // 1171
#define NSEC_PAD (NTILES * TILE_SECS)  // padded; pad sectors stay zero
#define MAXN 4000000

// One fused clearable state region: [sectors | status | ticket]
#define STATE_U32 (NSEC_PAD * 8u + NTILES + 1u)
__device__ unsigned g_state[STATE_U32];
__device__ unsigned g_packed[MAXN];    // per-point (key<<3)|off
__device__ unsigned g_total;

__device__ __forceinline__ unsigned* secPtr()    { return g_state; }
__device__ __forceinline__ unsigned* statusPtr() { return g_state + NSEC_PAD * 8u; }
__device__ __forceinline__ unsigned* ticketPtr() { return g_state + NSEC_PAD * 8u + NTILES; }

// ---- pass A: key/off per point, mark sector bitmap (u32 REDG atomics) -----
#define KA_P 8
__global__ void kA(const int4* __restrict__ coords, int n) {
    int base = (blockIdx.x * blockDim.x + threadIdx.x) * KA_P;
    if (base >= n) return;
    int m = n - base; if (m > KA_P) m = KA_P;
    int4 c[KA_P];
#pragma unroll
    for (int j = 0; j < KA_P; j++)
        c[j] = (j < m) ? __ldcs(&coords[base + j]) : make_int4(0, 0, 0, 0);
    unsigned key[KA_P], off[KA_P];
#pragma unroll
    for (int j = 0; j < KA_P; j++) {
        off[j] = (unsigned)((c[j].y & 1) | ((c[j].z & 1) << 1) | ((c[j].w & 1) << 2));
        key[j] = (((unsigned)c[j].x * HALF + (unsigned)(c[j].w >> 1)) * HALF
                  + (unsigned)(c[j].z >> 1)) * HALF + (unsigned)(c[j].y >> 1);
    }
#pragma unroll
    for (int j = 0; j < KA_P; j++)
        if (j < m) g_packed[base + j] = (key[j] << 3) | off[j];
#pragma unroll
    for (int j = 0; j < KA_P; j++)
        if (j < m) {
            unsigned s = key[j] / KPS, rem = key[j] % KPS;
            atomicOr(&secPtr()[s * 8u + 1u + (rem >> 5)], 1u << (rem & 31u));  // REDG
        }
}

// ---- fused scan + compact over sectors: decoupled lookback ----------------
__global__ void __launch_bounds__(SCT) kScan(float4* __restrict__ cout) {
    __shared__ unsigned s_tile;
    __shared__ unsigned s_warpsum[SCT / 32];
    __shared__ unsigned s_excl;

    if (threadIdx.x == 0) s_tile = atomicAdd(ticketPtr(), 1u);
    __syncthreads();
    const unsigned tile = s_tile;
    const unsigned sec0 = tile * TILE_SECS + threadIdx.x * SEC_PER_T;

    uint4 qa[SEC_PER_T], qb[SEC_PER_T];
    {
        const uint4* p = reinterpret_cast<const uint4*>(&secPtr()[(size_t)sec0 * 8u]);
#pragma unroll
        for (int j = 0; j < SEC_PER_T; j++) { qa[j] = p[2 * j]; qb[j] = p[2 * j + 1]; }
    }
    unsigned pcs[SEC_PER_T], s = 0;
#pragma unroll
    for (int j = 0; j < SEC_PER_T; j++) {
        unsigned t = __popc(qa[j].y) + __popc(qa[j].z) + __popc(qa[j].w)
                   + __popc(qb[j].x) + __popc(qb[j].y) + __popc(qb[j].z) + __popc(qb[j].w);
        pcs[j] = t; s += t;
    }

    // block-wide exclusive scan of per-thread sums
    const unsigned lane = threadIdx.x & 31u, wid = threadIdx.x >> 5;
    unsigned inc = s;
#pragma unroll
    for (int d = 1; d < 32; d <<= 1) {
        unsigned x = __shfl_up_sync(0xffffffffu, inc, d);
        if (lane >= (unsigned)d) inc += x;
    }
    if (lane == 31) s_warpsum[wid] = inc;
    __syncthreads();
    if (threadIdx.x < SCT / 32) {
        unsigned v = s_warpsum[threadIdx.x];
#pragma unroll
        for (int d = 1; d < SCT / 32; d <<= 1) {
            unsigned x = __shfl_up_sync(0xffffu, v, d);
            if (threadIdx.x >= (unsigned)d) v += x;
        }
        s_warpsum[threadIdx.x] = v;
    }
    __syncthreads();
    const unsigned threadExcl = (wid ? s_warpsum[wid - 1] : 0u) + (inc - s);
    const unsigned tileAgg = s_warpsum[SCT / 32 - 1];

    unsigned* status = statusPtr();
    if (threadIdx.x == 0) {
        if (tile == 0) {
            atomicExch(&status[0], (tileAgg << 2) | 2u);
            s_excl = 0u;
            if (NTILES == 1) g_total = tileAgg;
        } else {
            atomicExch(&status[tile], (tileAgg << 2) | 1u);
        }
    }

    if (wid == 0 && tile > 0) {
        unsigned excl = 0;
        int look = (int)tile - 1;
        for (;;) {
            int idx = look - (int)lane;
            unsigned stv;
            do {
                stv = (idx >= 0) ? *(volatile unsigned*)&status[idx] : 2u;
            } while (__any_sync(0xffffffffu, (stv & 3u) == 0u));
            unsigned incMask = __ballot_sync(0xffffffffu, (stv & 3u) == 2u);
            if (incMask) {
                int firstInc = __ffs(incMask) - 1;
                unsigned contrib = (lane <= (unsigned)firstInc && idx >= 0) ? (stv >> 2) : 0u;
#pragma unroll
                for (int d = 16; d; d >>= 1) contrib += __shfl_down_sync(0xffffffffu, contrib, d);
                excl += __shfl_sync(0xffffffffu, contrib, 0);
                break;
            } else {
                unsigned contrib = (idx >= 0) ? (stv >> 2) : 0u;
#pragma unroll
                for (int d = 16; d; d >>= 1) contrib += __shfl_down_sync(0xffffffffu, contrib, d);
                excl += __shfl_sync(0xffffffffu, contrib, 0);
                look -= 32;
            }
        }
        if (lane == 0) {
            atomicExch(&status[tile], ((excl + tileAgg) << 2) | 2u);
            s_excl = excl;
            if (tile == NTILES - 1) g_total = excl + tileAgg;
        }
    }
    __syncthreads();

    unsigned r = s_excl + threadExcl;
#pragma unroll
    for (int j = 0; j < SEC_PER_T; j++) {
        // write this sector's rank-prefix field (owned by this thread)
        secPtr()[(size_t)(sec0 + j) * 8u] = r;
        unsigned words[7] = {qa[j].y, qa[j].z, qa[j].w, qb[j].x, qb[j].y, qb[j].z, qb[j].w};
        unsigned secbase = (sec0 + j) * KPS;
#pragma unroll
        for (int wj = 0; wj < 7; wj++) {
            unsigned w = words[wj];
            unsigned kb = secbase + wj * 32u;
            while (w) {
                unsigned b = (unsigned)__ffs(w) - 1u;
                w &= w - 1u;
                unsigned key = kb + b;
                __stcs(&cout[r], make_float4((float)(key >> 27),
                                             (float)(key & 511u),
                                             (float)((key >> 9) & 511u),
                                             (float)((key >> 18) & 511u)));
                r++;
            }
        }
    }
}

// ---- pass B: ONE-sector rank gather + feats scatter-add + pad -------------
#define KB_P 4
__global__ void kB(const float* __restrict__ kw, float* __restrict__ feats,
                   float4* __restrict__ cout, int n) {
    int base = (blockIdx.x * blockDim.x + threadIdx.x) * KB_P;
    if (base >= n) return;
    int m = n - base; if (m > KB_P) m = KB_P;
    unsigned pk[KB_P];
#pragma unroll
    for (int j = 0; j < KB_P; j++)
        pk[j] = (j < m) ? g_packed[base + j] : 0u;
    uint4 qa[KB_P], qb[KB_P];
    unsigned rem[KB_P];
#pragma unroll
    for (int j = 0; j < KB_P; j++) {
        unsigned key = pk[j] >> 3;
        unsigned sct = key / KPS;
        rem[j] = key % KPS;
        const uint4* gp = reinterpret_cast<const uint4*>(&secPtr()[(size_t)sct * 8u]);
        qa[j] = __ldg(gp);
        qb[j] = __ldg(gp + 1);
    }
    unsigned total = g_total;
#pragma unroll
    for (int j = 0; j < KB_P; j++) {
        if (j >= m) continue;
        unsigned off = pk[j] & 7u;
        unsigned wi = rem[j] >> 5, b = rem[j] & 31u;
        unsigned words[7] = {qa[j].y, qa[j].z, qa[j].w, qb[j].x, qb[j].y, qb[j].z, qb[j].w};
        unsigned partial = (1u << b) - 1u;
        unsigned r = qa[j].x;
#pragma unroll
        for (unsigned t = 0; t < 7u; t++) {
            unsigned mask = (t < wi) ? 0xffffffffu : ((t == wi) ? partial : 0u);
            r += __popc(words[t] & mask);
        }
        float contrib = (float)(1u << off) * __ldg(&kw[off]);
        atomicAdd(&feats[r], contrib);  // REDG
        if ((unsigned)(base + j) >= total)
            __stcs(&cout[base + j], make_float4(-1.f, -1.f, -1.f, -1.f));
    }
}

extern "C" void kernel_launch(void* const* d_in, const int* in_sizes, int n_in,
                              void* d_out, int out_size) {
    const int4*  coords = (const int4*)d_in[0];
    const float* kw     = (const float*)d_in[1];
    float* out = (float*)d_out;
    int n = in_sizes[0] / 4;                 // number of points
    float* feats = out + (size_t)4 * n;      // layout: coords (N,4) then feats (N,1)

    cudaMemsetAsync(feats, 0, (size_t)n * sizeof(float), 0);

    const int TB = 256;
    kA<<<(n + TB * KA_P - 1) / (TB * KA_P), TB>>>(coords, n);
    kScan<<<NTILES, SCT>>>((float4*)out);
    kB<<<(n + TB * KB_P - 1) / (TB * KB_P), TB>>>(kw, feats, (float4*)out, n);

    // clear sectors + lookback status + ticket for the next graph replay
    void* statePtr = nullptr;
    cudaGetSymbolAddress(&statePtr, g_state);
    cudaMemsetAsync(statePtr, 0, (size_t)STATE_U32 * sizeof(unsigned), 0);
}

// round 11
// speedup vs baseline: 1.1752x; 1.1752x over previous
#include <cuda_runtime.h>

// FOG: stride-2 occupancy downsample of 4M sparse voxels.
// v7 = v4 layout (64MB word bitmap + per-4-word prefix) with L2-residency play:
//  - custom plain-store clear kernel (keeps bitmap L2-resident for next replay)
//  - feats zeroing folded into kA
//  - streaming hints only on pure streams (coords, packed, cout)

#define HALF 512
#define NWORDS (1u << 23)             // 2^29 keys / 64 bits per word (64 MB)
#define TILE_T 512
#define TILE_I 8
#define TILE_WORDS (TILE_T * TILE_I)  // 4096 words per tile
#define NTILES (NWORDS / TILE_WORDS)  // 2048
#define MAXN 4000000

// One fused clearable state region: [bits | status | ticket], padded to 32B
#define STATE_U64 (NWORDS + (NTILES + 1) / 2 + 1)
#define STATE_U64_PAD ((STATE_U64 + 3) & ~3u)
__device__ unsigned long long g_state[STATE_U64_PAD];
__device__ unsigned int g_prefix4[NWORDS / 4];  // 8.4 MB: rank at each 4-word group
__device__ unsigned int g_packed[MAXN];         // 16 MB per-point (key<<3)|off
__device__ unsigned int g_total;

__device__ __forceinline__ unsigned long long* bitsPtr() { return g_state; }
__device__ __forceinline__ unsigned* statusPtr() { return (unsigned*)(g_state + NWORDS); }
__device__ __forceinline__ unsigned* ticketPtr() { return (unsigned*)(g_state + NWORDS + (NTILES + 1) / 2); }

// ---- pass A: zero feats + key/off per point + mark bitmap (REDG) ----------
#define KA_P 4
__global__ void kA(const int4* __restrict__ coords, float* __restrict__ feats, int n) {
    int base = (blockIdx.x * blockDim.x + threadIdx.x) * KA_P;
    if (base >= n) return;
    int m = n - base; if (m > KA_P) m = KA_P;
    // zero this thread's slice of feats (n divisible by 4 in practice; guard anyway)
    if (m == KA_P) {
        *reinterpret_cast<float4*>(&feats[base]) = make_float4(0.f, 0.f, 0.f, 0.f);
    } else {
        for (int j = 0; j < m; j++) feats[base + j] = 0.f;
    }
    int4 c[KA_P];
#pragma unroll
    for (int j = 0; j < KA_P; j++)
        c[j] = (j < m) ? __ldcs(&coords[base + j]) : make_int4(0, 0, 0, 0);
    unsigned key[KA_P], off[KA_P];
#pragma unroll
    for (int j = 0; j < KA_P; j++) {
        off[j] = (unsigned)((c[j].y & 1) | ((c[j].z & 1) << 1) | ((c[j].w & 1) << 2));
        key[j] = (((unsigned)c[j].x * HALF + (unsigned)(c[j].w >> 1)) * HALF
                  + (unsigned)(c[j].z >> 1)) * HALF + (unsigned)(c[j].y >> 1);
    }
#pragma unroll
    for (int j = 0; j < KA_P; j++)
        if (j < m) __stcs(&g_packed[base + j], (key[j] << 3) | off[j]);
#pragma unroll
    for (int j = 0; j < KA_P; j++)
        if (j < m) atomicOr(&bitsPtr()[key[j] >> 6], 1ull << (key[j] & 63));  // REDG (result unused)
}

// ---- fused scan + compact: decoupled lookback -----------------------------
__global__ void __launch_bounds__(TILE_T) kScan(float4* __restrict__ cout) {
    __shared__ unsigned s_tile;
    __shared__ unsigned s_warpsum[TILE_T / 32];
    __shared__ unsigned s_excl;

    if (threadIdx.x == 0) s_tile = atomicAdd(ticketPtr(), 1u);
    __syncthreads();
    const unsigned tile = s_tile;
    const unsigned base = tile * TILE_WORDS + threadIdx.x * TILE_I;

    unsigned long long words[TILE_I];
    {
        const ulonglong2* p = reinterpret_cast<const ulonglong2*>(&bitsPtr()[base]);
#pragma unroll
        for (int j = 0; j < TILE_I / 2; j++) {
            ulonglong2 v = p[j];                  // plain load: keep bits L2-resident for kB
            words[2 * j] = v.x; words[2 * j + 1] = v.y;
        }
    }
    unsigned pc[TILE_I], s = 0;
#pragma unroll
    for (int j = 0; j < TILE_I; j++) { pc[j] = (unsigned)__popcll(words[j]); s += pc[j]; }

    // block-wide exclusive scan of per-thread sums
    const unsigned lane = threadIdx.x & 31u, wid = threadIdx.x >> 5;
    unsigned inc = s;
#pragma unroll
    for (int d = 1; d < 32; d <<= 1) {
        unsigned x = __shfl_up_sync(0xffffffffu, inc, d);
        if (lane >= (unsigned)d) inc += x;
    }
    if (lane == 31) s_warpsum[wid] = inc;
    __syncthreads();
    if (threadIdx.x < TILE_T / 32) {
        unsigned v = s_warpsum[threadIdx.x];
#pragma unroll
        for (int d = 1; d < TILE_T / 32; d <<= 1) {
            unsigned x = __shfl_up_sync((1u << (TILE_T / 32)) - 1u, v, d);
            if (threadIdx.x >= (unsigned)d) v += x;
        }
        s_warpsum[threadIdx.x] = v;
    }
    __syncthreads();
    const unsigned wordExcl = (wid ? s_warpsum[wid - 1] : 0u) + (inc - s);
    const unsigned tileAgg  = s_warpsum[TILE_T / 32 - 1];

    unsigned* status = statusPtr();
    if (threadIdx.x == 0) {
        if (tile == 0) {
            atomicExch(&status[0], (tileAgg << 2) | 2u);
            s_excl = 0u;
            if (NTILES == 1) g_total = tileAgg;
        } else {
            atomicExch(&status[tile], (tileAgg << 2) | 1u);
        }
    }

    // warp 0: decoupled lookback
    if (wid == 0 && tile > 0) {
        unsigned excl = 0;
        int look = (int)tile - 1;
        for (;;) {
            int idx = look - (int)lane;
            unsigned stv;
            do {
                stv = (idx >= 0) ? *(volatile unsigned*)&status[idx] : 2u;
            } while (__any_sync(0xffffffffu, (stv & 3u) == 0u));
            unsigned incMask = __ballot_sync(0xffffffffu, (stv & 3u) == 2u);
            if (incMask) {
                int firstInc = __ffs(incMask) - 1;
                unsigned contrib = (lane <= (unsigned)firstInc && idx >= 0) ? (stv >> 2) : 0u;
#pragma unroll
                for (int d = 16; d; d >>= 1) contrib += __shfl_down_sync(0xffffffffu, contrib, d);
                excl += __shfl_sync(0xffffffffu, contrib, 0);
                break;
            } else {
                unsigned contrib = (idx >= 0) ? (stv >> 2) : 0u;
#pragma unroll
                for (int d = 16; d; d >>= 1) contrib += __shfl_down_sync(0xffffffffu, contrib, d);
                excl += __shfl_sync(0xffffffffu, contrib, 0);
                look -= 32;
            }
        }
        if (lane == 0) {
            atomicExch(&status[tile], ((excl + tileAgg) << 2) | 2u);
            s_excl = excl;
            if (tile == NTILES - 1) g_total = excl + tileAgg;
        }
    }
    __syncthreads();

    unsigned rank = s_excl + wordExcl;

    // per-4-word prefix (plain stores -> L2-resident for kB)
    {
        unsigned g4 = base >> 2;
        g_prefix4[g4]     = rank;
        g_prefix4[g4 + 1] = rank + pc[0] + pc[1] + pc[2] + pc[3];
    }

    // emit compacted sorted coords (streaming stores)
    unsigned r = rank;
#pragma unroll
    for (int j = 0; j < TILE_I; j++) {
        unsigned long long word = words[j];
        unsigned keybase = (base + j) << 6;
        while (word) {
            unsigned b = (unsigned)__ffsll((long long)word) - 1u;
            word &= word - 1ull;
            unsigned key = keybase + b;
            float4 v = make_float4((float)(key >> 27),
                                   (float)(key & 511u),
                                   (float)((key >> 9) & 511u),
                                   (float)((key >> 18) & 511u));
            __stcs(&cout[r], v);
            r++;
        }
    }
}

// ---- pass B: rank gather + feats scatter-add + pad (2 pts/thread) ---------
#define KB_P 2
__global__ void kB(const float* __restrict__ kw, float* __restrict__ feats,
                   float4* __restrict__ cout, int n) {
    int base = (blockIdx.x * blockDim.x + threadIdx.x) * KB_P;
    if (base >= n) return;
    int m = n - base; if (m > KB_P) m = KB_P;
    unsigned p[KB_P];
#pragma unroll
    for (int j = 0; j < KB_P; j++)
        if (j < m) p[j] = __ldcs(&g_packed[base + j]);
    ulonglong2 lo[KB_P], hi[KB_P];
    unsigned pre[KB_P];
#pragma unroll
    for (int j = 0; j < KB_P; j++) {
        if (j >= m) continue;
        unsigned g4 = (p[j] >> 3) >> 8;  // key>>6>>2
        const ulonglong2* gp = reinterpret_cast<const ulonglong2*>(&bitsPtr()[(size_t)g4 << 2]);
        lo[j] = __ldg(gp);
        hi[j] = __ldg(gp + 1);
        pre[j] = __ldg(&g_prefix4[g4]);
    }
    unsigned total = g_total;
#pragma unroll
    for (int j = 0; j < KB_P; j++) {
        if (j >= m) continue;
        unsigned key = p[j] >> 3;
        unsigned off = p[j] & 7u;
        unsigned b = key & 63u;
        unsigned wi = (key >> 6) & 3u;
        unsigned r = pre[j];
        if (wi > 0) r += (unsigned)__popcll(lo[j].x);
        if (wi > 1) r += (unsigned)__popcll(lo[j].y);
        if (wi > 2) r += (unsigned)__popcll(hi[j].x);
        unsigned long long wsel = (wi == 0) ? lo[j].x : (wi == 1) ? lo[j].y
                                 : (wi == 2) ? hi[j].x : hi[j].y;
        r += (unsigned)__popcll(wsel & ((1ull << b) - 1ull));
        float contrib = (float)(1u << off) * __ldg(&kw[off]);
        atomicAdd(&feats[r], contrib);  // REDG
        if ((unsigned)(base + j) >= total)
            __stcs(&cout[base + j], make_float4(-1.f, -1.f, -1.f, -1.f));
    }
}

// ---- pass E: plain-store clear of [bits|status|ticket] --------------------
// Plain stores allocate in L2 with evict-normal -> next replay's kA atomics hit L2.
#define KE_V 4   // ulonglong2 (16B) stores per thread = 64B/thread
__global__ void kE() {
    const unsigned NU2 = STATE_U64_PAD / 2;  // number of 16B chunks
    unsigned i = (blockIdx.x * blockDim.x + threadIdx.x) * KE_V;
    ulonglong2* p = reinterpret_cast<ulonglong2*>(g_state);
#pragma unroll
    for (int j = 0; j < KE_V; j++)
        if (i + j < NU2) p[i + j] = make_ulonglong2(0ull, 0ull);
}

extern "C" void kernel_launch(void* const* d_in, const int* in_sizes, int n_in,
                              void* d_out, int out_size) {
    const int4*  coords = (const int4*)d_in[0];
    const float* kw     = (const float*)d_in[1];
    float* out = (float*)d_out;
    int n = in_sizes[0] / 4;                 // number of points
    float* feats = out + (size_t)4 * n;      // layout: coords (N,4) then feats (N,1)

    const int TB = 256;
    kA<<<(n + TB * KA_P - 1) / (TB * KA_P), TB>>>(coords, feats, n);
    kScan<<<NTILES, TILE_T>>>((float4*)out);
    kB<<<(n + TB * KB_P - 1) / (TB * KB_P), TB>>>(kw, feats, (float4*)out, n);
    const unsigned NU2 = STATE_U64_PAD / 2;
    kE<<<(NU2 + TB * KE_V - 1) / (TB * KE_V), TB>>>();
}